// round 1
// baseline (speedup 1.0000x reference)
#include <cuda_runtime.h>
#include <math.h>

#define NN 50000
#define NE 800000
#define D 128

// ---------------- device scratch (no allocations allowed) ----------------
__device__ int   g_deg_in[NN];
__device__ int   g_deg_out[NN];
__device__ int   g_row_ptr[NN + 1];
__device__ int   g_cursor[NN];
__device__ int   g_col[NE];
__device__ float g_invd1[NN];
__device__ float g_innorm[NN];
__device__ float g_outnorm[NN];
__device__ float g_v[NN];
__device__ float g_y1[NN * D];
__device__ float g_y2[NN * D];
__device__ float g_z[NN * D];
__device__ float g_Wt[D * D];
__device__ float g_Wc[D * D];
__device__ float g_bt[D];
__device__ float g_bw[D];

// ---------------- graph preprocessing ----------------
__global__ void k_zero() {
    int i = blockIdx.x * blockDim.x + threadIdx.x;
    if (i < NN) { g_deg_in[i] = 0; g_deg_out[i] = 0; g_cursor[i] = 0; }
}

__global__ void k_hist(const int* __restrict__ src, const int* __restrict__ dst) {
    int e = blockIdx.x * blockDim.x + threadIdx.x;
    if (e < NE) {
        atomicAdd(&g_deg_in[dst[e]], 1);
        atomicAdd(&g_deg_out[src[e]], 1);
    }
}

// Single-block exclusive scan of in-degrees -> row_ptr, plus per-node norms.
__global__ void k_scan() {
    __shared__ int warp_sums[32];
    __shared__ int s_run;
    int tid = threadIdx.x, lane = tid & 31, wid = tid >> 5;
    if (tid == 0) { s_run = 0; g_row_ptr[0] = 0; }
    __syncthreads();
    for (int base = 0; base < NN; base += 1024) {
        int i = base + tid;
        int v = (i < NN) ? g_deg_in[i] : 0;
        int incl = v;
        #pragma unroll
        for (int off = 1; off < 32; off <<= 1) {
            int t = __shfl_up_sync(0xffffffffu, incl, off);
            if (lane >= off) incl += t;
        }
        if (lane == 31) warp_sums[wid] = incl;
        __syncthreads();
        if (wid == 0) {
            int ws = warp_sums[lane];
            #pragma unroll
            for (int off = 1; off < 32; off <<= 1) {
                int t = __shfl_up_sync(0xffffffffu, ws, off);
                if (lane >= off) ws += t;
            }
            warp_sums[lane] = ws;
        }
        __syncthreads();
        int prev = (wid > 0) ? warp_sums[wid - 1] : 0;
        int my_incl = s_run + prev + incl;
        if (i < NN) g_row_ptr[i + 1] = my_incl;
        __syncthreads();
        if (tid == 1023) s_run = my_incl;
        __syncthreads();
    }
    for (int i = tid; i < NN; i += 1024) {
        int di = g_deg_in[i], dq = g_deg_out[i];
        g_invd1[i]   = 1.0f / (float)(di + 1);
        g_innorm[i]  = 1.0f / sqrtf((float)(di > 0 ? di : 1));
        g_outnorm[i] = 1.0f / sqrtf((float)(dq > 0 ? dq : 1));
    }
}

__global__ void k_scatter(const int* __restrict__ src, const int* __restrict__ dst) {
    int e = blockIdx.x * blockDim.x + threadIdx.x;
    if (e < NE) {
        int d = dst[e];
        int p = g_row_ptr[d] + atomicAdd(&g_cursor[d], 1);
        g_col[p] = src[e];
    }
}

// ---------------- tiny weight-space precompute ----------------
// g_Wt = W1 @ W2
__global__ void k_mmA(const float* __restrict__ A, const float* __restrict__ B) {
    int r = blockIdx.x, c = threadIdx.x;
    __shared__ float arow[D];
    arow[c] = A[r * D + c];
    __syncthreads();
    float acc = 0.f;
    #pragma unroll 8
    for (int k = 0; k < D; k++) acc += arow[k] * B[k * D + c];
    g_Wt[r * D + c] = acc;
}
// g_Wc = g_Wt @ W3
__global__ void k_mmB(const float* __restrict__ B) {
    int r = blockIdx.x, c = threadIdx.x;
    __shared__ float arow[D];
    arow[c] = g_Wt[r * D + c];
    __syncthreads();
    float acc = 0.f;
    #pragma unroll 8
    for (int k = 0; k < D; k++) acc += arow[k] * B[k * D + c];
    g_Wc[r * D + c] = acc;
}
// g_bt = b1 @ W2 + b2
__global__ void k_bias1(const float* __restrict__ b1, const float* __restrict__ W2,
                        const float* __restrict__ b2) {
    int c = threadIdx.x;
    float acc = b2[c];
    #pragma unroll 8
    for (int k = 0; k < D; k++) acc += b1[k] * W2[k * D + c];
    g_bt[c] = acc;
}
// g_bw = g_bt @ W3
__global__ void k_bias2(const float* __restrict__ W3) {
    int c = threadIdx.x;
    float acc = 0.f;
    #pragma unroll 8
    for (int k = 0; k < D; k++) acc += g_bt[k] * W3[k * D + c];
    g_bw[c] = acc;
}

// ---------------- aggregation passes (warp per node, gather-only) ----------------
// MODE 0: out = (sum_neigh + self) * invd1                          (SAGE pass 1)
// MODE 1: out = (sum_neigh + self) * invd1 * outnorm                (SAGE pass 2, pre-scaled for GCN)
// MODE 2: out = sum_neigh * innorm ; v = innorm * sum(outnorm[src]) (GraphConv)
template <int MODE>
__global__ void k_agg(const float* __restrict__ hin, float* __restrict__ hout) {
    int t = blockIdx.x * blockDim.x + threadIdx.x;
    int w = t >> 5;
    int lane = t & 31;
    if (w >= NN) return;
    const float4* in4 = (const float4*)hin;

    float4 acc;
    if (MODE < 2) acc = __ldg(&in4[(size_t)w * 32 + lane]);
    else          acc = make_float4(0.f, 0.f, 0.f, 0.f);
    float vs = 0.f;

    int e = g_row_ptr[w];
    int end = g_row_ptr[w + 1];

    for (; e + 3 < end; e += 4) {
        int s0 = __ldg(&g_col[e]);
        int s1 = __ldg(&g_col[e + 1]);
        int s2 = __ldg(&g_col[e + 2]);
        int s3 = __ldg(&g_col[e + 3]);
        float4 t0 = __ldg(&in4[(size_t)s0 * 32 + lane]);
        float4 t1 = __ldg(&in4[(size_t)s1 * 32 + lane]);
        float4 t2 = __ldg(&in4[(size_t)s2 * 32 + lane]);
        float4 t3 = __ldg(&in4[(size_t)s3 * 32 + lane]);
        if (MODE == 2)
            vs += (g_outnorm[s0] + g_outnorm[s1]) + (g_outnorm[s2] + g_outnorm[s3]);
        acc.x += (t0.x + t1.x) + (t2.x + t3.x);
        acc.y += (t0.y + t1.y) + (t2.y + t3.y);
        acc.z += (t0.z + t1.z) + (t2.z + t3.z);
        acc.w += (t0.w + t1.w) + (t2.w + t3.w);
    }
    for (; e < end; e++) {
        int s0 = __ldg(&g_col[e]);
        float4 t0 = __ldg(&in4[(size_t)s0 * 32 + lane]);
        if (MODE == 2) vs += g_outnorm[s0];
        acc.x += t0.x; acc.y += t0.y; acc.z += t0.z; acc.w += t0.w;
    }

    float sc;
    if (MODE == 0)      sc = g_invd1[w];
    else if (MODE == 1) sc = g_invd1[w] * g_outnorm[w];
    else {
        sc = g_innorm[w];
        if (lane == 0) g_v[w] = vs * sc;
    }
    acc.x *= sc; acc.y *= sc; acc.z *= sc; acc.w *= sc;
    ((float4*)hout)[(size_t)w * 32 + lane] = acc;
}

// ---------------- final fused GEMM: out = z @ Wc + v (x) bw + b3 ----------------
// 4 rows per warp; lane owns 4 output columns (float4).
__global__ void k_final(const float* __restrict__ b3, float* __restrict__ out) {
    int t = blockIdx.x * blockDim.x + threadIdx.x;
    int w = t >> 5;
    int lane = t & 31;
    int r0 = w * 4;
    if (r0 >= NN) return;

    const float4* Wc4 = (const float4*)g_Wc;
    const float4* z4 = (const float4*)g_z;

    float4 acc0 = make_float4(0.f, 0.f, 0.f, 0.f);
    float4 acc1 = acc0, acc2 = acc0, acc3 = acc0;

    #pragma unroll 4
    for (int k = 0; k < D; k += 4) {
        float4 z0 = __ldg(&z4[(size_t)(r0 + 0) * 32 + (k >> 2)]);
        float4 z1 = __ldg(&z4[(size_t)(r0 + 1) * 32 + (k >> 2)]);
        float4 z2 = __ldg(&z4[(size_t)(r0 + 2) * 32 + (k >> 2)]);
        float4 z3 = __ldg(&z4[(size_t)(r0 + 3) * 32 + (k >> 2)]);
        const float* p0 = (const float*)&z0;
        const float* p1 = (const float*)&z1;
        const float* p2 = (const float*)&z2;
        const float* p3 = (const float*)&z3;
        #pragma unroll
        for (int kk = 0; kk < 4; kk++) {
            float4 wv = __ldg(&Wc4[(size_t)(k + kk) * 32 + lane]);
            float a0 = p0[kk], a1 = p1[kk], a2 = p2[kk], a3 = p3[kk];
            acc0.x += a0 * wv.x; acc0.y += a0 * wv.y; acc0.z += a0 * wv.z; acc0.w += a0 * wv.w;
            acc1.x += a1 * wv.x; acc1.y += a1 * wv.y; acc1.z += a1 * wv.z; acc1.w += a1 * wv.w;
            acc2.x += a2 * wv.x; acc2.y += a2 * wv.y; acc2.z += a2 * wv.z; acc2.w += a2 * wv.w;
            acc3.x += a3 * wv.x; acc3.y += a3 * wv.y; acc3.z += a3 * wv.z; acc3.w += a3 * wv.w;
        }
    }

    float4 bwv = __ldg(&((const float4*)g_bw)[lane]);
    float4 b3v = __ldg(&((const float4*)b3)[lane]);
    float v0 = g_v[r0 + 0], v1 = g_v[r0 + 1], v2 = g_v[r0 + 2], v3 = g_v[r0 + 3];

    float4 o;
    float4* o4 = (float4*)out;
    o.x = acc0.x + v0 * bwv.x + b3v.x; o.y = acc0.y + v0 * bwv.y + b3v.y;
    o.z = acc0.z + v0 * bwv.z + b3v.z; o.w = acc0.w + v0 * bwv.w + b3v.w;
    o4[(size_t)(r0 + 0) * 32 + lane] = o;
    o.x = acc1.x + v1 * bwv.x + b3v.x; o.y = acc1.y + v1 * bwv.y + b3v.y;
    o.z = acc1.z + v1 * bwv.z + b3v.z; o.w = acc1.w + v1 * bwv.w + b3v.w;
    o4[(size_t)(r0 + 1) * 32 + lane] = o;
    o.x = acc2.x + v2 * bwv.x + b3v.x; o.y = acc2.y + v2 * bwv.y + b3v.y;
    o.z = acc2.z + v2 * bwv.z + b3v.z; o.w = acc2.w + v2 * bwv.w + b3v.w;
    o4[(size_t)(r0 + 2) * 32 + lane] = o;
    o.x = acc3.x + v3 * bwv.x + b3v.x; o.y = acc3.y + v3 * bwv.y + b3v.y;
    o.z = acc3.z + v3 * bwv.z + b3v.z; o.w = acc3.w + v3 * bwv.w + b3v.w;
    o4[(size_t)(r0 + 3) * 32 + lane] = o;
}

// ---------------- launch ----------------
extern "C" void kernel_launch(void* const* d_in, const int* in_sizes, int n_in,
                              void* d_out, int out_size) {
    const float* x  = (const float*)d_in[0];
    const float* W1 = (const float*)d_in[1];
    const float* b1 = (const float*)d_in[2];
    const float* W2 = (const float*)d_in[3];
    const float* b2 = (const float*)d_in[4];
    const float* W3 = (const float*)d_in[5];
    const float* b3 = (const float*)d_in[6];
    const int* src  = (const int*)d_in[7];
    const int* dst  = (const int*)d_in[8];
    float* out = (float*)d_out;

    float *y1, *y2, *z;
    cudaGetSymbolAddress((void**)&y1, g_y1);
    cudaGetSymbolAddress((void**)&y2, g_y2);
    cudaGetSymbolAddress((void**)&z,  g_z);

    // graph preprocessing
    k_zero<<<(NN + 255) / 256, 256>>>();
    k_hist<<<(NE + 255) / 256, 256>>>(src, dst);
    k_scan<<<1, 1024>>>();
    k_scatter<<<(NE + 255) / 256, 256>>>(src, dst);

    // weight-space precompute (independent of graph)
    k_mmA<<<D, D>>>(W1, W2);
    k_mmB<<<D, D>>>(W3);
    k_bias1<<<1, D>>>(b1, W2, b2);
    k_bias2<<<1, D>>>(W3);

    // three aggregation passes (warp per node)
    const int AGG_BLOCKS = (NN * 32 + 255) / 256;   // 6250
    k_agg<0><<<AGG_BLOCKS, 256>>>(x,  y1);
    k_agg<1><<<AGG_BLOCKS, 256>>>(y1, y2);
    k_agg<2><<<AGG_BLOCKS, 256>>>(y2, z);

    // fused final GEMM + bias terms
    const int FIN_WARPS = (NN + 3) / 4;             // 12500
    const int FIN_BLOCKS = (FIN_WARPS * 32 + 255) / 256;
    k_final<<<FIN_BLOCKS, 256>>>(b3, out);
}

// round 3
// speedup vs baseline: 1.9143x; 1.9143x over previous
#include <cuda_runtime.h>
#include <cuda_fp16.h>
#include <math.h>

#define NN 50000
#define NE 800000
#define D 128
#define NB 196   // (NN + 255) / 256

// ---------------- device scratch (no allocations allowed) ----------------
__device__ int    g_deg_in[NN];
__device__ int    g_deg_out[NN];
__device__ int    g_row_ptr[NN + 1];
__device__ int    g_cursor[NN];
__device__ int    g_col[NE];
__device__ int    g_bsum[NB];
__device__ int    g_boff[NB];
__device__ float  g_invd1[NN];
__device__ float  g_innorm[NN];
__device__ float  g_outnorm[NN];
__device__ __half g_t [NN * D];
__device__ __half g_y1[NN * D];
__device__ __half g_y2[NN * D];
__device__ float  g_Wt[D * D];
__device__ float  g_Wc[D * D];
__device__ float  g_bt[D];
__device__ float  g_bw[D];

__device__ __forceinline__ float4 h4_to_f4(uint2 u) {
    __half2 a = *(__half2*)&u.x;
    __half2 b = *(__half2*)&u.y;
    float2 fa = __half22float2(a), fb = __half22float2(b);
    return make_float4(fa.x, fa.y, fb.x, fb.y);
}
__device__ __forceinline__ uint2 f4_to_h4(float x, float y, float z, float w) {
    __half2 a = __floats2half2_rn(x, y);
    __half2 b = __floats2half2_rn(z, w);
    uint2 u;
    u.x = *(unsigned*)&a;
    u.y = *(unsigned*)&b;
    return u;
}

// ---------------- graph preprocessing ----------------
__global__ void k_zero() {
    int i = blockIdx.x * blockDim.x + threadIdx.x;
    if (i < NN) { g_deg_in[i] = 0; g_deg_out[i] = 0; }
}

__global__ void k_hist(const int* __restrict__ src, const int* __restrict__ dst) {
    int e = blockIdx.x * blockDim.x + threadIdx.x;
    if (e < NE) {
        atomicAdd(&g_deg_in[dst[e]], 1);
        atomicAdd(&g_deg_out[src[e]], 1);
    }
}

// per-block sums of in-degree
__global__ void k_partial() {
    __shared__ int ws[8];
    int tid = threadIdx.x, lane = tid & 31, wid = tid >> 5;
    int i = blockIdx.x * 256 + tid;
    int v = (i < NN) ? g_deg_in[i] : 0;
    #pragma unroll
    for (int off = 16; off > 0; off >>= 1) v += __shfl_down_sync(0xffffffffu, v, off);
    if (lane == 0) ws[wid] = v;
    __syncthreads();
    if (tid == 0) {
        int s = 0;
        #pragma unroll
        for (int j = 0; j < 8; j++) s += ws[j];
        g_bsum[blockIdx.x] = s;
    }
}

// exclusive scan of the NB block sums (single block, 256 threads)
__global__ void k_bscan() {
    __shared__ int ws[8];
    int tid = threadIdx.x, lane = tid & 31, wid = tid >> 5;
    int v = (tid < NB) ? g_bsum[tid] : 0;
    int incl = v;
    #pragma unroll
    for (int off = 1; off < 32; off <<= 1) {
        int t = __shfl_up_sync(0xffffffffu, incl, off);
        if (lane >= off) incl += t;
    }
    if (lane == 31) ws[wid] = incl;
    __syncthreads();
    if (wid == 0 && lane < 8) {
        int s = ws[lane];
        #pragma unroll
        for (int off = 1; off < 8; off <<= 1) {
            int t = __shfl_up_sync(0xffu, s, off);
            if (lane >= off) s += t;
        }
        ws[lane] = s;
    }
    __syncthreads();
    int total = incl + (wid > 0 ? ws[wid - 1] : 0);
    if (tid < NB) g_boff[tid] = total - v;   // exclusive
}

// row_ptr + cursor init + norms
__global__ void k_rowptr() {
    __shared__ int ws[8];
    int tid = threadIdx.x, lane = tid & 31, wid = tid >> 5;
    int i = blockIdx.x * 256 + tid;
    int v = (i < NN) ? g_deg_in[i] : 0;
    int incl = v;
    #pragma unroll
    for (int off = 1; off < 32; off <<= 1) {
        int t = __shfl_up_sync(0xffffffffu, incl, off);
        if (lane >= off) incl += t;
    }
    if (lane == 31) ws[wid] = incl;
    __syncthreads();
    if (wid == 0 && lane < 8) {
        int s = ws[lane];
        #pragma unroll
        for (int off = 1; off < 8; off <<= 1) {
            int t = __shfl_up_sync(0xffu, s, off);
            if (lane >= off) s += t;
        }
        ws[lane] = s;
    }
    __syncthreads();
    int base = g_boff[blockIdx.x] + (wid > 0 ? ws[wid - 1] : 0);
    if (i < NN) {
        int excl = base + incl - v;
        g_row_ptr[i + 1] = base + incl;
        g_cursor[i] = excl;           // scatter writes start here
        int di = v, dq = g_deg_out[i];
        g_invd1[i]   = 1.0f / (float)(di + 1);
        g_innorm[i]  = rsqrtf((float)(di > 0 ? di : 1));
        g_outnorm[i] = rsqrtf((float)(dq > 0 ? dq : 1));
    }
    if (i == 0) g_row_ptr[0] = 0;
}

__global__ void k_scatter(const int* __restrict__ src, const int* __restrict__ dst) {
    int e = blockIdx.x * blockDim.x + threadIdx.x;
    if (e < NE) {
        int p = atomicAdd(&g_cursor[dst[e]], 1);
        g_col[p] = src[e];
    }
}

// ---------------- tiny weight-space precompute ----------------
__global__ void k_mmA(const float* __restrict__ A, const float* __restrict__ B) {
    int r = blockIdx.x, c = threadIdx.x;
    __shared__ float arow[D];
    arow[c] = A[r * D + c];
    __syncthreads();
    float acc = 0.f;
    #pragma unroll 8
    for (int k = 0; k < D; k++) acc += arow[k] * B[k * D + c];
    g_Wt[r * D + c] = acc;
}
__global__ void k_mmB(const float* __restrict__ B) {
    int r = blockIdx.x, c = threadIdx.x;
    __shared__ float arow[D];
    arow[c] = g_Wt[r * D + c];
    __syncthreads();
    float acc = 0.f;
    #pragma unroll 8
    for (int k = 0; k < D; k++) acc += arow[k] * B[k * D + c];
    g_Wc[r * D + c] = acc;
}
__global__ void k_bias1(const float* __restrict__ b1, const float* __restrict__ W2,
                        const float* __restrict__ b2) {
    int c = threadIdx.x;
    float acc = b2[c];
    #pragma unroll 8
    for (int k = 0; k < D; k++) acc += b1[k] * W2[k * D + c];
    g_bt[c] = acc;
}
__global__ void k_bias2(const float* __restrict__ W3) {
    int c = threadIdx.x;
    float acc = 0.f;
    #pragma unroll 8
    for (int k = 0; k < D; k++) acc += g_bt[k] * W3[k * D + c];
    g_bw[c] = acc;
}

// ---------------- front GEMM: g_t = x @ Wc  (fp32 in, fp16 out) ----------------
__global__ void k_gemm(const float* __restrict__ x) {
    int t = blockIdx.x * blockDim.x + threadIdx.x;
    int w = t >> 5;
    int lane = t & 31;
    int r0 = w * 4;
    if (r0 >= NN) return;

    const float4* Wc4 = (const float4*)g_Wc;
    const float4* x4  = (const float4*)x;

    float4 acc0 = make_float4(0.f, 0.f, 0.f, 0.f);
    float4 acc1 = acc0, acc2 = acc0, acc3 = acc0;

    #pragma unroll 4
    for (int k = 0; k < D; k += 4) {
        float4 z0 = __ldg(&x4[(size_t)(r0 + 0) * 32 + (k >> 2)]);
        float4 z1 = __ldg(&x4[(size_t)(r0 + 1) * 32 + (k >> 2)]);
        float4 z2 = __ldg(&x4[(size_t)(r0 + 2) * 32 + (k >> 2)]);
        float4 z3 = __ldg(&x4[(size_t)(r0 + 3) * 32 + (k >> 2)]);
        const float* p0 = (const float*)&z0;
        const float* p1 = (const float*)&z1;
        const float* p2 = (const float*)&z2;
        const float* p3 = (const float*)&z3;
        #pragma unroll
        for (int kk = 0; kk < 4; kk++) {
            float4 wv = __ldg(&Wc4[(size_t)(k + kk) * 32 + lane]);
            float a0 = p0[kk], a1 = p1[kk], a2 = p2[kk], a3 = p3[kk];
            acc0.x += a0 * wv.x; acc0.y += a0 * wv.y; acc0.z += a0 * wv.z; acc0.w += a0 * wv.w;
            acc1.x += a1 * wv.x; acc1.y += a1 * wv.y; acc1.z += a1 * wv.z; acc1.w += a1 * wv.w;
            acc2.x += a2 * wv.x; acc2.y += a2 * wv.y; acc2.z += a2 * wv.z; acc2.w += a2 * wv.w;
            acc3.x += a3 * wv.x; acc3.y += a3 * wv.y; acc3.z += a3 * wv.z; acc3.w += a3 * wv.w;
        }
    }

    uint2* t4 = (uint2*)g_t;
    t4[(size_t)(r0 + 0) * 32 + lane] = f4_to_h4(acc0.x, acc0.y, acc0.z, acc0.w);
    t4[(size_t)(r0 + 1) * 32 + lane] = f4_to_h4(acc1.x, acc1.y, acc1.z, acc1.w);
    t4[(size_t)(r0 + 2) * 32 + lane] = f4_to_h4(acc2.x, acc2.y, acc2.z, acc2.w);
    t4[(size_t)(r0 + 3) * 32 + lane] = f4_to_h4(acc3.x, acc3.y, acc3.z, acc3.w);
}

// ---------------- aggregation passes (warp per node, gather-only, fp16) ----------------
// MODE 0: y1 = (sum_neigh + self) * invd1                                (SAGE 1)
// MODE 1: y2 = (sum_neigh + self) * invd1 * outnorm                      (SAGE 2, GCN-prescaled)
// MODE 2: out = innorm*sum_neigh + (innorm*sum outnorm[src])*bw + b3     (GraphConv + epilogue, fp32 out)
template <int MODE>
__global__ void k_agg(const __half* __restrict__ hin, __half* __restrict__ hout,
                      const float* __restrict__ b3, float* __restrict__ out) {
    int t = blockIdx.x * blockDim.x + threadIdx.x;
    int w = t >> 5;
    int lane = t & 31;
    if (w >= NN) return;
    const uint2* in4 = (const uint2*)hin;

    float4 acc = make_float4(0.f, 0.f, 0.f, 0.f);
    if (MODE < 2) {
        acc = h4_to_f4(__ldg(&in4[(size_t)w * 32 + lane]));
    }
    float vs = 0.f;

    int e = g_row_ptr[w];
    int end = g_row_ptr[w + 1];

    for (; e + 3 < end; e += 4) {
        int s0 = __ldg(&g_col[e]);
        int s1 = __ldg(&g_col[e + 1]);
        int s2 = __ldg(&g_col[e + 2]);
        int s3 = __ldg(&g_col[e + 3]);
        float4 t0 = h4_to_f4(__ldg(&in4[(size_t)s0 * 32 + lane]));
        float4 t1 = h4_to_f4(__ldg(&in4[(size_t)s1 * 32 + lane]));
        float4 t2 = h4_to_f4(__ldg(&in4[(size_t)s2 * 32 + lane]));
        float4 t3 = h4_to_f4(__ldg(&in4[(size_t)s3 * 32 + lane]));
        if (MODE == 2)
            vs += (g_outnorm[s0] + g_outnorm[s1]) + (g_outnorm[s2] + g_outnorm[s3]);
        acc.x += (t0.x + t1.x) + (t2.x + t3.x);
        acc.y += (t0.y + t1.y) + (t2.y + t3.y);
        acc.z += (t0.z + t1.z) + (t2.z + t3.z);
        acc.w += (t0.w + t1.w) + (t2.w + t3.w);
    }
    for (; e < end; e++) {
        int s0 = __ldg(&g_col[e]);
        float4 t0 = h4_to_f4(__ldg(&in4[(size_t)s0 * 32 + lane]));
        if (MODE == 2) vs += g_outnorm[s0];
        acc.x += t0.x; acc.y += t0.y; acc.z += t0.z; acc.w += t0.w;
    }

    if (MODE < 2) {
        float sc = (MODE == 0) ? g_invd1[w] : g_invd1[w] * g_outnorm[w];
        ((uint2*)hout)[(size_t)w * 32 + lane] =
            f4_to_h4(acc.x * sc, acc.y * sc, acc.z * sc, acc.w * sc);
    } else {
        float sc = g_innorm[w];
        float vb = vs * sc;
        float4 bwv = __ldg(&((const float4*)g_bw)[lane]);
        float4 b3v = __ldg(&((const float4*)b3)[lane]);
        float4 o;
        o.x = acc.x * sc + vb * bwv.x + b3v.x;
        o.y = acc.y * sc + vb * bwv.y + b3v.y;
        o.z = acc.z * sc + vb * bwv.z + b3v.z;
        o.w = acc.w * sc + vb * bwv.w + b3v.w;
        ((float4*)out)[(size_t)w * 32 + lane] = o;
    }
}

// ---------------- launch ----------------
extern "C" void kernel_launch(void* const* d_in, const int* in_sizes, int n_in,
                              void* d_out, int out_size) {
    const float* x  = (const float*)d_in[0];
    const float* W1 = (const float*)d_in[1];
    const float* b1 = (const float*)d_in[2];
    const float* W2 = (const float*)d_in[3];
    const float* b2 = (const float*)d_in[4];
    const float* W3 = (const float*)d_in[5];
    const float* b3 = (const float*)d_in[6];
    const int* src  = (const int*)d_in[7];
    const int* dst  = (const int*)d_in[8];
    float* out = (float*)d_out;

    __half *tptr, *y1, *y2;
    cudaGetSymbolAddress((void**)&tptr, g_t);
    cudaGetSymbolAddress((void**)&y1, g_y1);
    cudaGetSymbolAddress((void**)&y2, g_y2);

    // weight-space precompute (independent of graph)
    k_mmA<<<D, D>>>(W1, W2);
    k_mmB<<<D, D>>>(W3);
    k_bias1<<<1, D>>>(b1, W2, b2);
    k_bias2<<<1, D>>>(W3);

    // front GEMM: t = x @ Wc  (independent of graph preprocessing)
    const int FIN_WARPS = (NN + 3) / 4;
    const int FIN_BLOCKS = (FIN_WARPS * 32 + 255) / 256;
    k_gemm<<<FIN_BLOCKS, 256>>>(x);

    // graph preprocessing (CSR build, multi-block scan)
    k_zero<<<NB, 256>>>();
    k_hist<<<(NE + 255) / 256, 256>>>(src, dst);
    k_partial<<<NB, 256>>>();
    k_bscan<<<1, 256>>>();
    k_rowptr<<<NB, 256>>>();
    k_scatter<<<(NE + 255) / 256, 256>>>(src, dst);

    // three aggregation passes (warp per node), last one fused with epilogue
    const int AGG_BLOCKS = (NN * 32 + 255) / 256;   // 6250
    k_agg<0><<<AGG_BLOCKS, 256>>>(tptr, y1, nullptr, nullptr);
    k_agg<1><<<AGG_BLOCKS, 256>>>(y1, y2, nullptr, nullptr);
    k_agg<2><<<AGG_BLOCKS, 256>>>(y2, nullptr, b3, out);
}

// round 4
// speedup vs baseline: 2.2049x; 1.1518x over previous
#include <cuda_runtime.h>
#include <cuda_fp16.h>
#include <math.h>

#define NN 50000
#define NE 800000
#define D 128
#define NB 196   // (NN + 255) / 256

// ---------------- device scratch (no allocations allowed) ----------------
__device__ int    g_deg_in[NN];
__device__ int    g_deg_out[NN];
__device__ int    g_row_ptr[NN + 1];
__device__ int    g_cursor[NN];
__device__ int    g_col[NE];
__device__ int    g_bsum[NB];
__device__ int    g_boff[NB];
__device__ float  g_invd1[NN];
__device__ float  g_innorm[NN];
__device__ float  g_outnorm[NN];
__device__ __half g_t [NN * D];
__device__ __half g_y1[NN * D];
__device__ __half g_y2[NN * D];
__device__ float  g_Wt[D * D];
__device__ float  g_Wc[D * D];
__device__ float  g_bt[D];
__device__ float  g_bw[D];

__device__ __forceinline__ float4 h4_to_f4(uint2 u) {
    __half2 a = *(__half2*)&u.x;
    __half2 b = *(__half2*)&u.y;
    float2 fa = __half22float2(a), fb = __half22float2(b);
    return make_float4(fa.x, fa.y, fb.x, fb.y);
}
__device__ __forceinline__ uint2 f4_to_h4(float x, float y, float z, float w) {
    __half2 a = __floats2half2_rn(x, y);
    __half2 b = __floats2half2_rn(z, w);
    uint2 u;
    u.x = *(unsigned*)&a;
    u.y = *(unsigned*)&b;
    return u;
}

// ---------------- graph preprocessing (worker stream) ----------------
__global__ void k_zero() {
    int i = blockIdx.x * blockDim.x + threadIdx.x;
    if (i < NN) { g_deg_in[i] = 0; g_deg_out[i] = 0; }
}

__global__ void k_hist(const int* __restrict__ src, const int* __restrict__ dst) {
    int e = blockIdx.x * blockDim.x + threadIdx.x;
    if (e < NE) {
        atomicAdd(&g_deg_in[dst[e]], 1);
        atomicAdd(&g_deg_out[src[e]], 1);
    }
}

__global__ void k_partial() {
    __shared__ int ws[8];
    int tid = threadIdx.x, lane = tid & 31, wid = tid >> 5;
    int i = blockIdx.x * 256 + tid;
    int v = (i < NN) ? g_deg_in[i] : 0;
    #pragma unroll
    for (int off = 16; off > 0; off >>= 1) v += __shfl_down_sync(0xffffffffu, v, off);
    if (lane == 0) ws[wid] = v;
    __syncthreads();
    if (tid == 0) {
        int s = 0;
        #pragma unroll
        for (int j = 0; j < 8; j++) s += ws[j];
        g_bsum[blockIdx.x] = s;
    }
}

__global__ void k_bscan() {
    __shared__ int ws[8];
    int tid = threadIdx.x, lane = tid & 31, wid = tid >> 5;
    int v = (tid < NB) ? g_bsum[tid] : 0;
    int incl = v;
    #pragma unroll
    for (int off = 1; off < 32; off <<= 1) {
        int t = __shfl_up_sync(0xffffffffu, incl, off);
        if (lane >= off) incl += t;
    }
    if (lane == 31) ws[wid] = incl;
    __syncthreads();
    if (wid == 0 && lane < 8) {
        int s = ws[lane];
        #pragma unroll
        for (int off = 1; off < 8; off <<= 1) {
            int t = __shfl_up_sync(0xffu, s, off);
            if (lane >= off) s += t;
        }
        ws[lane] = s;
    }
    __syncthreads();
    int total = incl + (wid > 0 ? ws[wid - 1] : 0);
    if (tid < NB) g_boff[tid] = total - v;   // exclusive
}

__global__ void k_rowptr() {
    __shared__ int ws[8];
    int tid = threadIdx.x, lane = tid & 31, wid = tid >> 5;
    int i = blockIdx.x * 256 + tid;
    int v = (i < NN) ? g_deg_in[i] : 0;
    int incl = v;
    #pragma unroll
    for (int off = 1; off < 32; off <<= 1) {
        int t = __shfl_up_sync(0xffffffffu, incl, off);
        if (lane >= off) incl += t;
    }
    if (lane == 31) ws[wid] = incl;
    __syncthreads();
    if (wid == 0 && lane < 8) {
        int s = ws[lane];
        #pragma unroll
        for (int off = 1; off < 8; off <<= 1) {
            int t = __shfl_up_sync(0xffu, s, off);
            if (lane >= off) s += t;
        }
        ws[lane] = s;
    }
    __syncthreads();
    int base = g_boff[blockIdx.x] + (wid > 0 ? ws[wid - 1] : 0);
    if (i < NN) {
        int excl = base + incl - v;
        g_row_ptr[i + 1] = base + incl;
        g_cursor[i] = excl;
        int di = v, dq = g_deg_out[i];
        g_invd1[i]   = 1.0f / (float)(di + 1);
        g_innorm[i]  = rsqrtf((float)(di > 0 ? di : 1));
        g_outnorm[i] = rsqrtf((float)(dq > 0 ? dq : 1));
    }
    if (i == 0) g_row_ptr[0] = 0;
}

__global__ void k_scatter(const int* __restrict__ src, const int* __restrict__ dst) {
    int e = blockIdx.x * blockDim.x + threadIdx.x;
    if (e < NE) {
        int p = atomicAdd(&g_cursor[dst[e]], 1);
        g_col[p] = src[e];
    }
}

// ---------------- fused weight precompute (2 kernels, 129 blocks each) ----------------
// k_wA: rows 0..127 -> Wt[r] = W1[r] @ W2 ; row 128 -> bt = b1 @ W2 + b2
__global__ void k_wA(const float* __restrict__ W1, const float* __restrict__ b1,
                     const float* __restrict__ W2, const float* __restrict__ b2) {
    int r = blockIdx.x, c = threadIdx.x;
    __shared__ float arow[D];
    arow[c] = (r < D) ? W1[r * D + c] : b1[c];
    __syncthreads();
    float a0 = 0.f, a1 = 0.f, a2 = 0.f, a3 = 0.f;
    #pragma unroll 8
    for (int k = 0; k < D; k += 4) {
        a0 += arow[k + 0] * __ldg(&W2[(k + 0) * D + c]);
        a1 += arow[k + 1] * __ldg(&W2[(k + 1) * D + c]);
        a2 += arow[k + 2] * __ldg(&W2[(k + 2) * D + c]);
        a3 += arow[k + 3] * __ldg(&W2[(k + 3) * D + c]);
    }
    float acc = (a0 + a1) + (a2 + a3);
    if (r < D) g_Wt[r * D + c] = acc;
    else       g_bt[c] = acc + b2[c];
}
// k_wB: rows 0..127 -> Wc[r] = Wt[r] @ W3 ; row 128 -> bw = bt @ W3
__global__ void k_wB(const float* __restrict__ W3) {
    int r = blockIdx.x, c = threadIdx.x;
    __shared__ float arow[D];
    arow[c] = (r < D) ? g_Wt[r * D + c] : g_bt[c];
    __syncthreads();
    float a0 = 0.f, a1 = 0.f, a2 = 0.f, a3 = 0.f;
    #pragma unroll 8
    for (int k = 0; k < D; k += 4) {
        a0 += arow[k + 0] * __ldg(&W3[(k + 0) * D + c]);
        a1 += arow[k + 1] * __ldg(&W3[(k + 1) * D + c]);
        a2 += arow[k + 2] * __ldg(&W3[(k + 2) * D + c]);
        a3 += arow[k + 3] * __ldg(&W3[(k + 3) * D + c]);
    }
    float acc = (a0 + a1) + (a2 + a3);
    if (r < D) g_Wc[r * D + c] = acc;
    else       g_bw[c] = acc;
}

// ---------------- front GEMM: g_t = x @ Wc  (fp32 in, fp16 out) ----------------
__global__ void k_gemm(const float* __restrict__ x) {
    int t = blockIdx.x * blockDim.x + threadIdx.x;
    int w = t >> 5;
    int lane = t & 31;
    int r0 = w * 4;
    if (r0 >= NN) return;

    const float4* Wc4 = (const float4*)g_Wc;
    const float4* x4  = (const float4*)x;

    float4 acc0 = make_float4(0.f, 0.f, 0.f, 0.f);
    float4 acc1 = acc0, acc2 = acc0, acc3 = acc0;

    #pragma unroll 4
    for (int k = 0; k < D; k += 4) {
        float4 z0 = __ldg(&x4[(size_t)(r0 + 0) * 32 + (k >> 2)]);
        float4 z1 = __ldg(&x4[(size_t)(r0 + 1) * 32 + (k >> 2)]);
        float4 z2 = __ldg(&x4[(size_t)(r0 + 2) * 32 + (k >> 2)]);
        float4 z3 = __ldg(&x4[(size_t)(r0 + 3) * 32 + (k >> 2)]);
        const float* p0 = (const float*)&z0;
        const float* p1 = (const float*)&z1;
        const float* p2 = (const float*)&z2;
        const float* p3 = (const float*)&z3;
        #pragma unroll
        for (int kk = 0; kk < 4; kk++) {
            float4 wv = __ldg(&Wc4[(size_t)(k + kk) * 32 + lane]);
            float a0 = p0[kk], a1 = p1[kk], a2 = p2[kk], a3 = p3[kk];
            acc0.x += a0 * wv.x; acc0.y += a0 * wv.y; acc0.z += a0 * wv.z; acc0.w += a0 * wv.w;
            acc1.x += a1 * wv.x; acc1.y += a1 * wv.y; acc1.z += a1 * wv.z; acc1.w += a1 * wv.w;
            acc2.x += a2 * wv.x; acc2.y += a2 * wv.y; acc2.z += a2 * wv.z; acc2.w += a2 * wv.w;
            acc3.x += a3 * wv.x; acc3.y += a3 * wv.y; acc3.z += a3 * wv.z; acc3.w += a3 * wv.w;
        }
    }

    uint2* t4 = (uint2*)g_t;
    t4[(size_t)(r0 + 0) * 32 + lane] = f4_to_h4(acc0.x, acc0.y, acc0.z, acc0.w);
    t4[(size_t)(r0 + 1) * 32 + lane] = f4_to_h4(acc1.x, acc1.y, acc1.z, acc1.w);
    t4[(size_t)(r0 + 2) * 32 + lane] = f4_to_h4(acc2.x, acc2.y, acc2.z, acc2.w);
    t4[(size_t)(r0 + 3) * 32 + lane] = f4_to_h4(acc3.x, acc3.y, acc3.z, acc3.w);
}

// ---------------- aggregation passes (warp per node, gather-only, fp16) ----------------
template <int MODE>
__global__ void k_agg(const __half* __restrict__ hin, __half* __restrict__ hout,
                      const float* __restrict__ b3, float* __restrict__ out) {
    int t = blockIdx.x * blockDim.x + threadIdx.x;
    int w = t >> 5;
    int lane = t & 31;
    if (w >= NN) return;
    const uint2* in4 = (const uint2*)hin;

    float4 acc = make_float4(0.f, 0.f, 0.f, 0.f);
    if (MODE < 2) {
        acc = h4_to_f4(__ldg(&in4[(size_t)w * 32 + lane]));
    }
    float vs = 0.f;

    int e = g_row_ptr[w];
    int end = g_row_ptr[w + 1];

    for (; e + 3 < end; e += 4) {
        int s0 = __ldg(&g_col[e]);
        int s1 = __ldg(&g_col[e + 1]);
        int s2 = __ldg(&g_col[e + 2]);
        int s3 = __ldg(&g_col[e + 3]);
        float4 t0 = h4_to_f4(__ldg(&in4[(size_t)s0 * 32 + lane]));
        float4 t1 = h4_to_f4(__ldg(&in4[(size_t)s1 * 32 + lane]));
        float4 t2 = h4_to_f4(__ldg(&in4[(size_t)s2 * 32 + lane]));
        float4 t3 = h4_to_f4(__ldg(&in4[(size_t)s3 * 32 + lane]));
        if (MODE == 2)
            vs += (g_outnorm[s0] + g_outnorm[s1]) + (g_outnorm[s2] + g_outnorm[s3]);
        acc.x += (t0.x + t1.x) + (t2.x + t3.x);
        acc.y += (t0.y + t1.y) + (t2.y + t3.y);
        acc.z += (t0.z + t1.z) + (t2.z + t3.z);
        acc.w += (t0.w + t1.w) + (t2.w + t3.w);
    }
    for (; e < end; e++) {
        int s0 = __ldg(&g_col[e]);
        float4 t0 = h4_to_f4(__ldg(&in4[(size_t)s0 * 32 + lane]));
        if (MODE == 2) vs += g_outnorm[s0];
        acc.x += t0.x; acc.y += t0.y; acc.z += t0.z; acc.w += t0.w;
    }

    if (MODE < 2) {
        float sc = (MODE == 0) ? g_invd1[w] : g_invd1[w] * g_outnorm[w];
        ((uint2*)hout)[(size_t)w * 32 + lane] =
            f4_to_h4(acc.x * sc, acc.y * sc, acc.z * sc, acc.w * sc);
    } else {
        float sc = g_innorm[w];
        float vb = vs * sc;
        float4 bwv = __ldg(&((const float4*)g_bw)[lane]);
        float4 b3v = __ldg(&((const float4*)b3)[lane]);
        float4 o;
        o.x = acc.x * sc + vb * bwv.x + b3v.x;
        o.y = acc.y * sc + vb * bwv.y + b3v.y;
        o.z = acc.z * sc + vb * bwv.z + b3v.z;
        o.w = acc.w * sc + vb * bwv.w + b3v.w;
        ((float4*)out)[(size_t)w * 32 + lane] = o;
    }
}

// ---------------- launch ----------------
extern "C" void kernel_launch(void* const* d_in, const int* in_sizes, int n_in,
                              void* d_out, int out_size) {
    const float* x  = (const float*)d_in[0];
    const float* W1 = (const float*)d_in[1];
    const float* b1 = (const float*)d_in[2];
    const float* W2 = (const float*)d_in[3];
    const float* b2 = (const float*)d_in[4];
    const float* W3 = (const float*)d_in[5];
    const float* b3 = (const float*)d_in[6];
    const int* src  = (const int*)d_in[7];
    const int* dst  = (const int*)d_in[8];
    float* out = (float*)d_out;

    __half *tptr, *y1, *y2;
    cudaGetSymbolAddress((void**)&tptr, g_t);
    cudaGetSymbolAddress((void**)&y1, g_y1);
    cudaGetSymbolAddress((void**)&y2, g_y2);

    // one-time host resources (no device memory involved)
    static cudaStream_t s1 = 0;
    static cudaEvent_t evA = 0, evB = 0;
    if (!s1) {
        cudaStreamCreateWithFlags(&s1, cudaStreamNonBlocking);
        cudaEventCreateWithFlags(&evA, cudaEventDisableTiming);
        cudaEventCreateWithFlags(&evB, cudaEventDisableTiming);
    }

    // ---- fork: CSR build on worker stream s1 ----
    cudaEventRecord(evA, 0);
    cudaStreamWaitEvent(s1, evA, 0);
    k_zero   <<<NB, 256, 0, s1>>>();
    k_hist   <<<(NE + 255) / 256, 256, 0, s1>>>(src, dst);
    k_partial<<<NB, 256, 0, s1>>>();
    k_bscan  <<<1, 256, 0, s1>>>();
    k_rowptr <<<NB, 256, 0, s1>>>();
    k_scatter<<<(NE + 255) / 256, 256, 0, s1>>>(src, dst);
    cudaEventRecord(evB, s1);

    // ---- main stream: weights -> front GEMM ----
    k_wA<<<D + 1, D>>>(W1, b1, W2, b2);
    k_wB<<<D + 1, D>>>(W3);

    const int FIN_WARPS = (NN + 3) / 4;
    const int FIN_BLOCKS = (FIN_WARPS * 32 + 255) / 256;
    k_gemm<<<FIN_BLOCKS, 256>>>(x);

    // ---- join: agg passes need both GEMM output and CSR ----
    cudaStreamWaitEvent(0, evB, 0);

    const int AGG_BLOCKS = (NN * 32 + 255) / 256;   // 6250
    k_agg<0><<<AGG_BLOCKS, 256>>>(tptr, y1, nullptr, nullptr);
    k_agg<1><<<AGG_BLOCKS, 256>>>(y1, y2, nullptr, nullptr);
    k_agg<2><<<AGG_BLOCKS, 256>>>(y2, nullptr, b3, out);
}

// round 5
// speedup vs baseline: 2.2301x; 1.0114x over previous
#include <cuda_runtime.h>
#include <cuda_fp16.h>
#include <math.h>

#define NN 50000
#define NE 800000
#define D 128
#define NB 196   // (NN + 255) / 256

// ---------------- device scratch (no allocations allowed) ----------------
__device__ int    g_deg_in[NN];
__device__ int    g_deg_out[NN];
__device__ int    g_row_ptr[NN + 1];
__device__ int    g_cursor[NN];
__device__ int    g_col[NE];
__device__ int    g_bsum[NB];
__device__ float  g_invd1[NN];
__device__ float  g_innorm[NN];
__device__ float  g_outnorm[NN];
__device__ __half g_t [NN * D];
__device__ __half g_y1[NN * D];
__device__ __half g_y2[NN * D];
__device__ float  g_Wt[D * D];
__device__ float  g_Wc[D * D];
__device__ float  g_bt[D];
__device__ float  g_bw[D];

__device__ __forceinline__ uint2 f4_to_h4(float x, float y, float z, float w) {
    __half2 a = __floats2half2_rn(x, y);
    __half2 b = __floats2half2_rn(z, w);
    uint2 u;
    u.x = *(unsigned*)&a;
    u.y = *(unsigned*)&b;
    return u;
}

__device__ __forceinline__ void add_h8(float* a, uint4 v) {
    __half2* h = (__half2*)&v;
    #pragma unroll
    for (int i = 0; i < 4; i++) {
        float2 f = __half22float2(h[i]);
        a[2 * i]     += f.x;
        a[2 * i + 1] += f.y;
    }
}

// ---------------- graph preprocessing (worker stream) ----------------
__global__ void k_hist(const int* __restrict__ src, const int* __restrict__ dst) {
    int i = blockIdx.x * blockDim.x + threadIdx.x;
    if (i < NE / 2) {
        int2 s = __ldg(&((const int2*)src)[i]);
        int2 d = __ldg(&((const int2*)dst)[i]);
        atomicAdd(&g_deg_in[d.x], 1);
        atomicAdd(&g_deg_in[d.y], 1);
        atomicAdd(&g_deg_out[s.x], 1);
        atomicAdd(&g_deg_out[s.y], 1);
    }
}

__global__ void k_partial() {
    __shared__ int ws[8];
    int tid = threadIdx.x, lane = tid & 31, wid = tid >> 5;
    int i = blockIdx.x * 256 + tid;
    int v = (i < NN) ? g_deg_in[i] : 0;
    #pragma unroll
    for (int off = 16; off > 0; off >>= 1) v += __shfl_down_sync(0xffffffffu, v, off);
    if (lane == 0) ws[wid] = v;
    __syncthreads();
    if (tid == 0) {
        int s = 0;
        #pragma unroll
        for (int j = 0; j < 8; j++) s += ws[j];
        g_bsum[blockIdx.x] = s;
    }
}

// fused: block base = sum of g_bsum[0..bid) computed in-kernel; then intra-block scan
__global__ void k_rowptr() {
    __shared__ int ws[8];
    __shared__ int s_base;
    int tid = threadIdx.x, lane = tid & 31, wid = tid >> 5;

    // block-exclusive base
    int v0 = (tid < blockIdx.x) ? g_bsum[tid] : 0;   // blockIdx.x <= 195 < 256
    #pragma unroll
    for (int off = 16; off > 0; off >>= 1) v0 += __shfl_down_sync(0xffffffffu, v0, off);
    if (lane == 0) ws[wid] = v0;
    __syncthreads();
    if (tid == 0) {
        int s = 0;
        #pragma unroll
        for (int j = 0; j < 8; j++) s += ws[j];
        s_base = s;
    }
    __syncthreads();

    // intra-block inclusive scan
    int i = blockIdx.x * 256 + tid;
    int v = (i < NN) ? g_deg_in[i] : 0;
    int incl = v;
    #pragma unroll
    for (int off = 1; off < 32; off <<= 1) {
        int t = __shfl_up_sync(0xffffffffu, incl, off);
        if (lane >= off) incl += t;
    }
    if (lane == 31) ws[wid] = incl;
    __syncthreads();
    if (wid == 0 && lane < 8) {
        int s = ws[lane];
        #pragma unroll
        for (int off = 1; off < 8; off <<= 1) {
            int t = __shfl_up_sync(0xffu, s, off);
            if (lane >= off) s += t;
        }
        ws[lane] = s;
    }
    __syncthreads();
    int base = s_base + (wid > 0 ? ws[wid - 1] : 0);
    if (i < NN) {
        int excl = base + incl - v;
        g_row_ptr[i + 1] = base + incl;
        g_cursor[i] = excl;
        int di = v, dq = g_deg_out[i];
        g_invd1[i]   = 1.0f / (float)(di + 1);
        g_innorm[i]  = rsqrtf((float)(di > 0 ? di : 1));
        g_outnorm[i] = rsqrtf((float)(dq > 0 ? dq : 1));
    }
    if (i == 0) g_row_ptr[0] = 0;
}

__global__ void k_scatter(const int* __restrict__ src, const int* __restrict__ dst) {
    int i = blockIdx.x * blockDim.x + threadIdx.x;
    if (i < NE / 2) {
        int2 s = __ldg(&((const int2*)src)[i]);
        int2 d = __ldg(&((const int2*)dst)[i]);
        int p0 = atomicAdd(&g_cursor[d.x], 1);
        g_col[p0] = s.x;
        int p1 = atomicAdd(&g_cursor[d.y], 1);
        g_col[p1] = s.y;
    }
}

// ---------------- fused weight precompute (2 kernels, 129 blocks each) ----------------
__global__ void k_wA(const float* __restrict__ W1, const float* __restrict__ b1,
                     const float* __restrict__ W2, const float* __restrict__ b2) {
    int r = blockIdx.x, c = threadIdx.x;
    __shared__ float arow[D];
    arow[c] = (r < D) ? W1[r * D + c] : b1[c];
    __syncthreads();
    float a0 = 0.f, a1 = 0.f, a2 = 0.f, a3 = 0.f;
    #pragma unroll 8
    for (int k = 0; k < D; k += 4) {
        a0 += arow[k + 0] * __ldg(&W2[(k + 0) * D + c]);
        a1 += arow[k + 1] * __ldg(&W2[(k + 1) * D + c]);
        a2 += arow[k + 2] * __ldg(&W2[(k + 2) * D + c]);
        a3 += arow[k + 3] * __ldg(&W2[(k + 3) * D + c]);
    }
    float acc = (a0 + a1) + (a2 + a3);
    if (r < D) g_Wt[r * D + c] = acc;
    else       g_bt[c] = acc + b2[c];
}
__global__ void k_wB(const float* __restrict__ W3) {
    int r = blockIdx.x, c = threadIdx.x;
    __shared__ float arow[D];
    arow[c] = (r < D) ? g_Wt[r * D + c] : g_bt[c];
    __syncthreads();
    float a0 = 0.f, a1 = 0.f, a2 = 0.f, a3 = 0.f;
    #pragma unroll 8
    for (int k = 0; k < D; k += 4) {
        a0 += arow[k + 0] * __ldg(&W3[(k + 0) * D + c]);
        a1 += arow[k + 1] * __ldg(&W3[(k + 1) * D + c]);
        a2 += arow[k + 2] * __ldg(&W3[(k + 2) * D + c]);
        a3 += arow[k + 3] * __ldg(&W3[(k + 3) * D + c]);
    }
    float acc = (a0 + a1) + (a2 + a3);
    if (r < D) g_Wc[r * D + c] = acc;
    else       g_bw[c] = acc;
}

// ---------------- front GEMM: g_t = x @ Wc  (fp32 in, fp16 out) ----------------
__global__ void k_gemm(const float* __restrict__ x) {
    int t = blockIdx.x * blockDim.x + threadIdx.x;
    int w = t >> 5;
    int lane = t & 31;
    int r0 = w * 4;
    if (r0 >= NN) return;

    const float4* Wc4 = (const float4*)g_Wc;
    const float4* x4  = (const float4*)x;

    float4 acc0 = make_float4(0.f, 0.f, 0.f, 0.f);
    float4 acc1 = acc0, acc2 = acc0, acc3 = acc0;

    #pragma unroll 4
    for (int k = 0; k < D; k += 4) {
        float4 z0 = __ldg(&x4[(size_t)(r0 + 0) * 32 + (k >> 2)]);
        float4 z1 = __ldg(&x4[(size_t)(r0 + 1) * 32 + (k >> 2)]);
        float4 z2 = __ldg(&x4[(size_t)(r0 + 2) * 32 + (k >> 2)]);
        float4 z3 = __ldg(&x4[(size_t)(r0 + 3) * 32 + (k >> 2)]);
        const float* p0 = (const float*)&z0;
        const float* p1 = (const float*)&z1;
        const float* p2 = (const float*)&z2;
        const float* p3 = (const float*)&z3;
        #pragma unroll
        for (int kk = 0; kk < 4; kk++) {
            float4 wv = __ldg(&Wc4[(size_t)(k + kk) * 32 + lane]);
            float a0 = p0[kk], a1 = p1[kk], a2 = p2[kk], a3 = p3[kk];
            acc0.x += a0 * wv.x; acc0.y += a0 * wv.y; acc0.z += a0 * wv.z; acc0.w += a0 * wv.w;
            acc1.x += a1 * wv.x; acc1.y += a1 * wv.y; acc1.z += a1 * wv.z; acc1.w += a1 * wv.w;
            acc2.x += a2 * wv.x; acc2.y += a2 * wv.y; acc2.z += a2 * wv.z; acc2.w += a2 * wv.w;
            acc3.x += a3 * wv.x; acc3.y += a3 * wv.y; acc3.z += a3 * wv.z; acc3.w += a3 * wv.w;
        }
    }

    uint2* t4 = (uint2*)g_t;
    t4[(size_t)(r0 + 0) * 32 + lane] = f4_to_h4(acc0.x, acc0.y, acc0.z, acc0.w);
    t4[(size_t)(r0 + 1) * 32 + lane] = f4_to_h4(acc1.x, acc1.y, acc1.z, acc1.w);
    t4[(size_t)(r0 + 2) * 32 + lane] = f4_to_h4(acc2.x, acc2.y, acc2.z, acc2.w);
    t4[(size_t)(r0 + 3) * 32 + lane] = f4_to_h4(acc3.x, acc3.y, acc3.z, acc3.w);
}

// ---------------- aggregation passes (half-warp per node, 128-bit loads, prefetch) --------
// MODE 0: y1 = (sum_neigh + self) * invd1
// MODE 1: y2 = (sum_neigh + self) * invd1 * outnorm
// MODE 2: out = innorm*sum_neigh + (innorm*sum outnorm[src])*bw + b3  (fp32 out)
template <int MODE>
__global__ __launch_bounds__(256) void k_agg(const __half* __restrict__ hin,
                                             __half* __restrict__ hout,
                                             const float* __restrict__ b3,
                                             float* __restrict__ out) {
    int t = blockIdx.x * 256 + threadIdx.x;
    int w = t >> 5;                       // global warp id
    int lane = threadIdx.x & 31;
    int sl = lane & 15;                   // sub-lane within half-warp
    int node = w * 2 + (lane >> 4);       // 2 nodes per warp
    if (node >= NN) return;

    const uint4* in8 = (const uint4*)hin; // 16B = 8 halves; row = 16 uint4

    float acc[8] = {0.f, 0.f, 0.f, 0.f, 0.f, 0.f, 0.f, 0.f};
    if (MODE < 2) add_h8(acc, __ldg(&in8[(size_t)node * 16 + sl]));
    float vs = 0.f;

    int e   = g_row_ptr[node];
    int end = g_row_ptr[node + 1];

    while (e < end) {
        int cols[8];
        #pragma unroll
        for (int j = 0; j < 8; j++)
            cols[j] = (e + j < end) ? __ldg(&g_col[e + j]) : -1;
        #pragma unroll
        for (int j = 0; j < 8; j++) {
            if (cols[j] >= 0) {
                uint4 v = __ldg(&in8[(size_t)cols[j] * 16 + sl]);
                add_h8(acc, v);
                if (MODE == 2) vs += g_outnorm[cols[j]];
            }
        }
        e += 8;
    }

    if (MODE < 2) {
        float sc = (MODE == 0) ? g_invd1[node] : g_invd1[node] * g_outnorm[node];
        uint4 u;
        __half2* h = (__half2*)&u;
        #pragma unroll
        for (int i = 0; i < 4; i++)
            h[i] = __floats2half2_rn(acc[2 * i] * sc, acc[2 * i + 1] * sc);
        ((uint4*)hout)[(size_t)node * 16 + sl] = u;
    } else {
        float sc = g_innorm[node];
        float vb = vs * sc;
        const float4* bw4 = (const float4*)g_bw;
        const float4* b34 = (const float4*)b3;
        float4 bwa = __ldg(&bw4[sl * 2]),     b3a = __ldg(&b34[sl * 2]);
        float4 bwb = __ldg(&bw4[sl * 2 + 1]), b3b = __ldg(&b34[sl * 2 + 1]);
        float4 o;
        float4* o4 = (float4*)out;
        o.x = acc[0] * sc + vb * bwa.x + b3a.x;
        o.y = acc[1] * sc + vb * bwa.y + b3a.y;
        o.z = acc[2] * sc + vb * bwa.z + b3a.z;
        o.w = acc[3] * sc + vb * bwa.w + b3a.w;
        o4[(size_t)node * 32 + sl * 2] = o;
        o.x = acc[4] * sc + vb * bwb.x + b3b.x;
        o.y = acc[5] * sc + vb * bwb.y + b3b.y;
        o.z = acc[6] * sc + vb * bwb.z + b3b.z;
        o.w = acc[7] * sc + vb * bwb.w + b3b.w;
        o4[(size_t)node * 32 + sl * 2 + 1] = o;
    }
}

// ---------------- launch ----------------
extern "C" void kernel_launch(void* const* d_in, const int* in_sizes, int n_in,
                              void* d_out, int out_size) {
    const float* x  = (const float*)d_in[0];
    const float* W1 = (const float*)d_in[1];
    const float* b1 = (const float*)d_in[2];
    const float* W2 = (const float*)d_in[3];
    const float* b2 = (const float*)d_in[4];
    const float* W3 = (const float*)d_in[5];
    const float* b3 = (const float*)d_in[6];
    const int* src  = (const int*)d_in[7];
    const int* dst  = (const int*)d_in[8];
    float* out = (float*)d_out;

    __half *tptr, *y1, *y2;
    void *din, *dout_deg;
    cudaGetSymbolAddress((void**)&tptr, g_t);
    cudaGetSymbolAddress((void**)&y1, g_y1);
    cudaGetSymbolAddress((void**)&y2, g_y2);
    cudaGetSymbolAddress(&din, g_deg_in);
    cudaGetSymbolAddress(&dout_deg, g_deg_out);

    // one-time host resources (no device memory involved)
    static cudaStream_t s1 = 0;
    static cudaEvent_t evA = 0, evB = 0;
    if (!s1) {
        cudaStreamCreateWithFlags(&s1, cudaStreamNonBlocking);
        cudaEventCreateWithFlags(&evA, cudaEventDisableTiming);
        cudaEventCreateWithFlags(&evB, cudaEventDisableTiming);
    }

    // ---- fork: CSR build on worker stream s1 ----
    cudaEventRecord(evA, 0);
    cudaStreamWaitEvent(s1, evA, 0);
    cudaMemsetAsync(din, 0, NN * sizeof(int), s1);
    cudaMemsetAsync(dout_deg, 0, NN * sizeof(int), s1);
    k_hist   <<<(NE / 2 + 255) / 256, 256, 0, s1>>>(src, dst);
    k_partial<<<NB, 256, 0, s1>>>();
    k_rowptr <<<NB, 256, 0, s1>>>();
    k_scatter<<<(NE / 2 + 255) / 256, 256, 0, s1>>>(src, dst);
    cudaEventRecord(evB, s1);

    // ---- main stream: weights -> front GEMM ----
    k_wA<<<D + 1, D>>>(W1, b1, W2, b2);
    k_wB<<<D + 1, D>>>(W3);

    const int FIN_WARPS = (NN + 3) / 4;
    const int FIN_BLOCKS = (FIN_WARPS * 32 + 255) / 256;
    k_gemm<<<FIN_BLOCKS, 256>>>(x);

    // ---- join: agg passes need both GEMM output and CSR ----
    cudaStreamWaitEvent(0, evB, 0);

    const int AGG_WARPS = (NN + 1) / 2;                    // 25000
    const int AGG_BLOCKS = (AGG_WARPS * 32 + 255) / 256;   // 3125
    k_agg<0><<<AGG_BLOCKS, 256>>>(tptr, y1, nullptr, nullptr);
    k_agg<1><<<AGG_BLOCKS, 256>>>(y1, y2, nullptr, nullptr);
    k_agg<2><<<AGG_BLOCKS, 256>>>(y2, nullptr, b3, out);
}